// round 6
// baseline (speedup 1.0000x reference)
#include <cuda_runtime.h>

// ---------------- static config ----------------
namespace cfg {
constexpr int NN = 10000;       // nodes
constexpr int NE = 128000;      // edges
constexpr int NWARP = 16;       // warps per conv block (8 pairs)
constexpr int NPAIR = NWARP / 2;
constexpr int CONV_THREADS = NWARP * 32;
constexpr int EPG = 8;          // edges per pair-group
constexpr int WS = 1800;        // per-pair scratch floats (even -> 8B alignment holds)
// smem floats: W1dup(48*64*2) + W2(64*416 permuted) + B1(64) + B2(416) + pair scratch
constexpr int SMEM_FLOATS = 48*64*2 + 64*416 + 64 + 416 + NPAIR*WS;
constexpr int SMEM_BYTES = SMEM_FLOATS * 4;   // 190592
}

typedef unsigned long long ull;

__device__ __forceinline__ ull pk2(float lo, float hi) {
    ull r; asm("mov.b64 %0, {%1,%2};" : "=l"(r) : "f"(lo), "f"(hi)); return r;
}
__device__ __forceinline__ float2 upk2(ull v) {
    float2 f; asm("mov.b64 {%0,%1}, %2;" : "=f"(f.x), "=f"(f.y) : "l"(v)); return f;
}
__device__ __forceinline__ ull ffma2(ull a, ull b, ull c) {
    ull d; asm("fma.rn.f32x2 %0, %1, %2, %3;" : "=l"(d) : "l"(a), "l"(b), "l"(c)); return d;
}
__device__ __forceinline__ void pair_bar(int id) {
    asm volatile("bar.sync %0, 64;" :: "r"(id) : "memory");
}

// ---------------- device scratch (no allocations allowed) ----------------
__device__ float g_h0[cfg::NN * 16];
__device__ float g_h1[cfg::NN * 12];
__device__ float g_acc0[cfg::NN * 16];
__device__ float g_acc1[cfg::NN * 12];
__device__ float g_cnt[cfg::NN];
__device__ float g_eattr[cfg::NE * 16];
__device__ float g_y1[cfg::NE * 3];

// ---------------- zero scratch ----------------
__global__ void zero_kernel() {
    int i = blockIdx.x * blockDim.x + threadIdx.x;
    int stride = gridDim.x * blockDim.x;
    for (int t = i; t < cfg::NN * 16; t += stride) g_acc0[t] = 0.f;
    for (int t = i; t < cfg::NN * 12; t += stride) { g_acc1[t] = 0.f; g_h1[t] = 0.f; }
    for (int t = i; t < cfg::NN; t += stride) g_cnt[t] = 0.f;
}

// ---------------- node encoder + node_embedding MLP ----------------
__global__ void node_init_kernel(const float* __restrict__ nf,
                                 const float* __restrict__ encW, const float* __restrict__ encB,
                                 const float* __restrict__ W1, const float* __restrict__ B1,
                                 const float* __restrict__ W2, const float* __restrict__ B2) {
    int n = blockIdx.x * blockDim.x + threadIdx.x;
    if (n >= cfg::NN) return;
    float enc[16];
    #pragma unroll
    for (int c = 0; c < 16; c++) enc[c] = encB[c];
    for (int f = 0; f < 64; f++) {
        float v = nf[n * 64 + f];
        #pragma unroll
        for (int c = 0; c < 16; c++) enc[c] = fmaf(v, encW[f * 16 + c], enc[c]);
    }
    float t[16];
    #pragma unroll
    for (int c = 0; c < 16; c++) {
        float a = B1[c];
        #pragma unroll
        for (int j = 0; j < 16; j++) a = fmaf(enc[j], W1[j * 16 + c], a);
        t[c] = fmaxf(a, 0.f);
    }
    #pragma unroll
    for (int c = 0; c < 16; c++) {
        float a = B2[c];
        #pragma unroll
        for (int j = 0; j < 16; j++) a = fmaf(t[j], W2[j * 16 + c], a);
        g_h0[n * 16 + c] = a;
    }
}

// ---------------- per-edge: geometry, rbf, edge_attr, degree count ----------------
__global__ void edge_init_kernel(const float* __restrict__ pos,
                                 const float* __restrict__ eain, const int* __restrict__ ei,
                                 const float* __restrict__ eeW1, const float* __restrict__ eeB1,
                                 const float* __restrict__ eeW2, const float* __restrict__ eeB2,
                                 const float* __restrict__ reW1, const float* __restrict__ reB1,
                                 const float* __restrict__ reW2, const float* __restrict__ reB2) {
    int e = blockIdx.x * blockDim.x + threadIdx.x;
    if (e >= cfg::NE) return;
    int sn = ei[e], dn = ei[cfg::NE + e];
    float vx = pos[sn * 3 + 0] - pos[dn * 3 + 0];
    float vy = pos[sn * 3 + 1] - pos[dn * 3 + 1];
    float vz = pos[sn * 3 + 2] - pos[dn * 3 + 2];
    float d = sqrtf(vx * vx + vy * vy + vz * vz);
    float dmx = fmaxf(d, 1e-9f);
    float s = 1.7320508075688772f / dmx;     // sqrt(3) * unit
    g_y1[e * 3 + 0] = s * vx;
    g_y1[e * 3 + 1] = s * vy;
    g_y1[e * 3 + 2] = s * vz;
    atomicAdd(&g_cnt[sn], 1.f);

    float xin[16];
    #pragma unroll
    for (int j = 0; j < 16; j++) xin[j] = eain[e * 16 + j];
    float he[16];
    #pragma unroll
    for (int c = 0; c < 16; c++) {
        float a = eeB1[c];
        #pragma unroll
        for (int j = 0; j < 16; j++) a = fmaf(xin[j], eeW1[j * 16 + c], a);
        he[c] = fmaxf(a, 0.f);
    }
    const float step = 12.0f / 31.0f;
    const float coeff = -0.5f / (step * step);
    float hr[16];
    #pragma unroll
    for (int c = 0; c < 16; c++) hr[c] = reB1[c];
    #pragma unroll 4
    for (int r = 0; r < 32; r++) {
        float t = d - (float)r * step;
        float rb = __expf(coeff * t * t);
        #pragma unroll
        for (int c = 0; c < 16; c++) hr[c] = fmaf(rb, reW1[r * 16 + c], hr[c]);
    }
    #pragma unroll
    for (int c = 0; c < 16; c++) hr[c] = fmaxf(hr[c], 0.f);
    #pragma unroll
    for (int c = 0; c < 16; c++) {
        float a = eeB2[c] + reB2[c];
        #pragma unroll
        for (int j = 0; j < 16; j++)
            a = fmaf(he[j], eeW2[j * 16 + c], fmaf(hr[j], reW2[j * 16 + c], a));
        g_eattr[e * 16 + c] = a;
    }
}

// ---------------- conv layer: warp-pair cooperative version ----------------
// fc2 weight smem layout (per k row of 416):
//   [0,384): 6 column-pairs interleaved: dest = j*64 + lane*2 + s  <= src col i=2j+s
//   [384,416): scalar block i=12 at original position
// Warp pair (role 0/1): role r owns fc2 pairs j=3r..3r+2 (role1 also scalar i=12).
__global__ void __launch_bounds__(cfg::CONV_THREADS, 1)
conv_kernel(const int* __restrict__ ei,
            const float* __restrict__ W1g, const float* __restrict__ B1g,
            const float* __restrict__ W2g, const float* __restrict__ B2g) {
    extern __shared__ float smem[];
    ull*   sW1d = (ull*)smem;            // [48][64] duplicated pairs (6144 floats)
    float* sW2  = smem + 6144;           // [64][416] permuted
    float* sB1  = sW2 + 26624;           // [64]
    float* sB2  = sB1 + 64;              // [416]
    float* sWS  = sB2 + 416;

    for (int t = threadIdx.x; t < 3072; t += blockDim.x) {
        float w = W1g[t];
        sW1d[t] = pk2(w, w);
    }
    for (int t = threadIdx.x; t < 64; t += blockDim.x) sB1[t] = B1g[t];
    for (int t = threadIdx.x; t < 26624; t += blockDim.x) {
        int k = t / 416, p = t - k * 416;
        int dest;
        if (p < 384) {
            int i = p >> 5, l = p & 31;
            dest = k * 416 + (i >> 1) * 64 + l * 2 + (i & 1);
        } else {
            dest = t;
        }
        sW2[dest] = W2g[t];
    }
    for (int t = threadIdx.x; t < 416; t += blockDim.x) sB2[t] = B2g[t];
    __syncthreads();

    const int lane = threadIdx.x & 31;
    const int warp = threadIdx.x >> 5;
    const int pair = warp >> 1;
    const int role = warp & 1;
    const int barid = 1 + pair;

    float* ws    = sWS + pair * cfg::WS;
    float* s_ea  = ws;          // [48][8] interleaved: s_ea[c*8+e]
    float* s_h   = ws + 384;    // [64][18] dup pairs: s_h[k*18+2e{,+1}] = h[k][e]
    float* s_x1  = ws + 1536;   // [8][4][3]
    float* s_y1  = ws + 1632;   // [8][3]
    float* s_dot = ws + 1656;   // [8][4]
    float* s_cr  = ws + 1688;   // [8][4][3]
    int*   s_idx = (int*)(ws + 1784); // [16]: src 0..7, dst 8..15

    const unsigned FULL = 0xffffffffu;
    const int numGroups = cfg::NE / cfg::EPG;   // 16000
    const int pairsTotal = gridDim.x * cfg::NPAIR;

    const int myE = lane & 7;     // fixed per lane for gather loops
    const int cOff = lane >> 3;   // 0..3

    for (int g = blockIdx.x * cfg::NPAIR + pair; g < numGroups; g += pairsTotal) {
        const int ebase = g * cfg::EPG;

        // ---- phase 1 (split): gather + geometry ----
        if (role == 0) {
            // s_ea cols 0..31: edge_attr (c<16) + h0[src] (16..31)
            int sn_r = ei[ebase + myE];
            #pragma unroll
            for (int j = 0; j < 8; j++) {
                int c = 4 * j + cOff;
                float v = (c < 16) ? g_eattr[(ebase + myE) * 16 + c]
                                   : g_h0[sn_r * 16 + (c - 16)];
                s_ea[c * 8 + myE] = v;
            }
        } else {
            if (lane < 8)       s_idx[lane] = ei[ebase + lane];
            else if (lane < 16) s_idx[lane] = ei[cfg::NE + ebase + (lane - 8)];
            int dn_r = ei[cfg::NE + ebase + myE];
            #pragma unroll
            for (int j = 0; j < 4; j++) {
                int c = 32 + 4 * j + cOff;
                s_ea[c * 8 + myE] = g_h0[dn_r * 16 + (c - 32)];
            }
            if (lane < 24) {
                int e = lane / 3, m = lane - e * 3;
                s_y1[lane] = g_y1[(ebase + e) * 3 + m];
            }
            __syncwarp();
            {
                int e = lane >> 2, n = lane & 3;   // all 32 (e,n) pairs
                int dn = s_idx[8 + e];
                s_x1[e * 12 + n * 3 + 0] = g_h1[dn * 12 + n * 3 + 0];
                s_x1[e * 12 + n * 3 + 1] = g_h1[dn * 12 + n * 3 + 1];
                s_x1[e * 12 + n * 3 + 2] = g_h1[dn * 12 + n * 3 + 2];
            }
            __syncwarp();
            {
                int e = lane >> 2, n = lane & 3;
                float xa = s_x1[e * 12 + n * 3 + 0], xb = s_x1[e * 12 + n * 3 + 1], xc = s_x1[e * 12 + n * 3 + 2];
                float ya = s_y1[e * 3 + 0], yb = s_y1[e * 3 + 1], yc = s_y1[e * 3 + 2];
                s_dot[e * 4 + n] = (xa * ya + xb * yb + xc * yc) * 0.57735026918962576f;
                s_cr[e * 12 + n * 3 + 0] = (xb * yc - xc * yb) * 0.70710678118654752f;
                s_cr[e * 12 + n * 3 + 1] = (xc * ya - xa * yc) * 0.70710678118654752f;
                s_cr[e * 12 + n * 3 + 2] = (xa * yb - xb * ya) * 0.70710678118654752f;
            }
        }
        pair_bar(barid);

        // ---- fc1 (both roles): role r computes hidden k = 32r + lane for 8 edges ----
        {
            const int k = 32 * role + lane;
            float b = sB1[k];
            ull bb = pk2(b, b);
            ull hacc[4] = {bb, bb, bb, bb};
            #pragma unroll 6
            for (int c = 0; c < 48; c++) {
                ull wd = sW1d[c * 64 + k];
                #pragma unroll
                for (int p = 0; p < 4; p++) {
                    ull vp = *(const ull*)(s_ea + c * 8 + 2 * p);
                    hacc[p] = ffma2(vp, wd, hacc[p]);
                }
            }
            float* hrow = s_h + k * 18;
            #pragma unroll
            for (int p = 0; p < 4; p++) {
                float2 f = upk2(hacc[p]);
                f.x = fmaxf(f.x, 0.f); f.y = fmaxf(f.y, 0.f);
                *(ull*)(hrow + 4 * p)     = pk2(f.x, f.x);
                *(ull*)(hrow + 4 * p + 2) = pk2(f.y, f.y);
            }
        }
        pair_bar(barid);

        // ---- fc2 + tensor product (role split) ----
        if (role == 0) {
            // pairs j=0,1,2  -> i = 0..5 (part of w00)
            ull acc[cfg::EPG][3];
            #pragma unroll
            for (int jl = 0; jl < 3; jl++) {
                ull b2 = pk2(sB2[lane + 64 * jl], sB2[lane + 64 * jl + 32]);
                #pragma unroll
                for (int e = 0; e < cfg::EPG; e++) acc[e][jl] = b2;
            }
            #pragma unroll 2
            for (int k = 0; k < 64; k++) {
                const float* rw = sW2 + k * 416;
                ull w2p[3];
                #pragma unroll
                for (int jl = 0; jl < 3; jl++)
                    w2p[jl] = *(const ull*)(rw + jl * 64 + lane * 2);
                const float* hk = s_h + k * 18;
                #pragma unroll
                for (int e = 0; e < cfg::EPG; e++) {
                    ull hh = *(const ull*)(hk + 2 * e);
                    #pragma unroll
                    for (int jl = 0; jl < 3; jl++)
                        acc[e][jl] = ffma2(hh, w2p[jl], acc[e][jl]);
                }
            }
            // phase4 partial: w00 i=0..5 -> ro0 partial
            #pragma unroll
            for (int e = 0; e < cfg::EPG; e++) {
                float w[6];
                #pragma unroll
                for (int jl = 0; jl < 3; jl++) {
                    float2 f = upk2(acc[e][jl]);
                    w[2 * jl] = f.x; w[2 * jl + 1] = f.y;
                }
                const float* x0p = s_ea + 32 * 8 + e;   // h0[dst], stride 8
                float ro0 = 0.f;
                #pragma unroll
                for (int i = 0; i < 6; i++) {
                    int n = 2 * i + (lane >> 4);
                    float c = w[i] * x0p[n * 8];
                    ro0 += c + __shfl_xor_sync(FULL, c, 16);
                }
                int sn = s_idx[e];
                if (lane < 16)
                    atomicAdd(&g_acc0[sn * 16 + lane], 0.22360679774997896f * ro0);
            }
        } else {
            // pairs j=3,4,5 -> i = 6..11, plus scalar i=12
            ull acc[cfg::EPG][3];
            float accs[cfg::EPG];
            #pragma unroll
            for (int jl = 0; jl < 3; jl++) {
                ull b2 = pk2(sB2[lane + 64 * (3 + jl)], sB2[lane + 64 * (3 + jl) + 32]);
                #pragma unroll
                for (int e = 0; e < cfg::EPG; e++) acc[e][jl] = b2;
            }
            {
                float bs = sB2[384 + lane];
                #pragma unroll
                for (int e = 0; e < cfg::EPG; e++) accs[e] = bs;
            }
            #pragma unroll 2
            for (int k = 0; k < 64; k++) {
                const float* rw = sW2 + k * 416;
                ull w2p[3];
                #pragma unroll
                for (int jl = 0; jl < 3; jl++)
                    w2p[jl] = *(const ull*)(rw + (3 + jl) * 64 + lane * 2);
                float w2s = rw[384 + lane];
                const float* hk = s_h + k * 18;
                #pragma unroll
                for (int e = 0; e < cfg::EPG; e++) {
                    ull hh = *(const ull*)(hk + 2 * e);
                    float h = hk[2 * e];
                    #pragma unroll
                    for (int jl = 0; jl < 3; jl++)
                        acc[e][jl] = ffma2(hh, w2p[jl], acc[e][jl]);
                    accs[e] = fmaf(h, w2s, accs[e]);
                }
            }
            // phase4: i = 6..12 -> rest of w00, w011, w101, w110, w111
            #pragma unroll
            for (int e = 0; e < cfg::EPG; e++) {
                float w[7];
                #pragma unroll
                for (int jl = 0; jl < 3; jl++) {
                    float2 f = upk2(acc[e][jl]);
                    w[2 * jl] = f.x; w[2 * jl + 1] = f.y;   // i = 6+2jl, 7+2jl
                }
                w[6] = accs[e];                              // i = 12

                const float* x0p = s_ea + 32 * 8 + e;
                float ro0 = 0.f, rt = 0.f, r1a = 0.f, r1b = 0.f, r1c = 0.f;
                // i=6,7: w00 tail
                #pragma unroll
                for (int i = 6; i < 8; i++) {
                    int n = 2 * i + (lane >> 4);
                    float c = w[i - 6] * x0p[n * 8];
                    ro0 += c + __shfl_xor_sync(FULL, c, 16);
                }
                // i=8,9: w011 -> t011[o=lane&3]
                #pragma unroll
                for (int i = 8; i < 10; i++) {
                    int n = ((i - 8) * 32 + lane) >> 2;
                    float c = w[i - 6] * x0p[n * 8];
                    c += __shfl_xor_sync(FULL, c, 4);
                    c += __shfl_xor_sync(FULL, c, 8);
                    c += __shfl_xor_sync(FULL, c, 16);
                    rt += c;
                }
                {   // i=10: low lanes w101 (n=lane/4,o=lane&3), high lanes w110 (n=0)
                    float wv = w[4];
                    float c = (lane >= 16) ? wv * s_dot[e * 4 + 0] : 0.f;
                    ro0 += c + __shfl_xor_sync(FULL, c, 16);
                    int n = (lane & 15) >> 2;
                    const float* xp = s_x1 + e * 12 + n * 3;
                    float m0 = (lane < 16) ? wv * xp[0] : 0.f;
                    float m1 = (lane < 16) ? wv * xp[1] : 0.f;
                    float m2 = (lane < 16) ? wv * xp[2] : 0.f;
                    m0 += __shfl_xor_sync(FULL, m0, 4); m0 += __shfl_xor_sync(FULL, m0, 8);
                    m1 += __shfl_xor_sync(FULL, m1, 4); m1 += __shfl_xor_sync(FULL, m1, 8);
                    m2 += __shfl_xor_sync(FULL, m2, 4); m2 += __shfl_xor_sync(FULL, m2, 8);
                    r1a += m0; r1b += m1; r1c += m2;
                }
                {   // i=11: all w110, n = 1 (low) / 2 (high)
                    float c = w[5] * s_dot[e * 4 + ((lane < 16) ? 1 : 2)];
                    ro0 += c + __shfl_xor_sync(FULL, c, 16);
                }
                {   // i=12: low lanes w110 (n=3), high lanes w111
                    float wv = w[6];
                    float c = (lane < 16) ? wv * s_dot[e * 4 + 3] : 0.f;
                    ro0 += c + __shfl_xor_sync(FULL, c, 16);
                    int n = (lane & 15) >> 2;
                    const float* cp = s_cr + e * 12 + n * 3;
                    float m0 = (lane >= 16) ? wv * cp[0] : 0.f;
                    float m1 = (lane >= 16) ? wv * cp[1] : 0.f;
                    float m2 = (lane >= 16) ? wv * cp[2] : 0.f;
                    m0 += __shfl_xor_sync(FULL, m0, 4); m0 += __shfl_xor_sync(FULL, m0, 8); m0 += __shfl_xor_sync(FULL, m0, 16);
                    m1 += __shfl_xor_sync(FULL, m1, 4); m1 += __shfl_xor_sync(FULL, m1, 8); m1 += __shfl_xor_sync(FULL, m1, 16);
                    m2 += __shfl_xor_sync(FULL, m2, 4); m2 += __shfl_xor_sync(FULL, m2, 8); m2 += __shfl_xor_sync(FULL, m2, 16);
                    r1a += m0; r1b += m1; r1c += m2;
                }
                r1a += rt * s_y1[e * 3 + 0];
                r1b += rt * s_y1[e * 3 + 1];
                r1c += rt * s_y1[e * 3 + 2];

                int sn = s_idx[e];
                if (lane < 16)
                    atomicAdd(&g_acc0[sn * 16 + lane], 0.22360679774997896f * ro0);
                if (lane < 4) {
                    atomicAdd(&g_acc1[sn * 12 + lane * 3 + 0], 0.20412414523193150f * r1a);
                    atomicAdd(&g_acc1[sn * 12 + lane * 3 + 1], 0.20412414523193150f * r1b);
                    atomicAdd(&g_acc1[sn * 12 + lane * 3 + 2], 0.20412414523193150f * r1c);
                }
            }
        }
        pair_bar(barid);   // protect shared scratch from next iteration's phase1
    }
}

// ---------------- scatter-mean residual update, zero accumulators ----------------
__global__ void update_kernel() {
    int i = blockIdx.x * blockDim.x + threadIdx.x;
    if (i < cfg::NN * 16) {
        int n = i >> 4;
        float inv = 1.f / fmaxf(g_cnt[n], 1.f);
        g_h0[i] += g_acc0[i] * inv;
        g_acc0[i] = 0.f;
    }
    if (i < cfg::NN * 12) {
        int n = i / 12;
        float inv = 1.f / fmaxf(g_cnt[n], 1.f);
        g_h1[i] += g_acc1[i] * inv;
        g_acc1[i] = 0.f;
    }
}

// ---------------- final update + o3.Linear + sorter layout ----------------
__global__ void final_kernel(float* __restrict__ out,
                             const float* __restrict__ lin0, const float* __restrict__ lin1) {
    int n = blockIdx.x * blockDim.x + threadIdx.x;
    if (n >= cfg::NN) return;
    float inv = 1.f / fmaxf(g_cnt[n], 1.f);
    float h0f[16];
    #pragma unroll
    for (int s = 0; s < 16; s++) h0f[s] = g_h0[n * 16 + s] + g_acc0[n * 16 + s] * inv;
    float h1f[12];
    #pragma unroll
    for (int s = 0; s < 12; s++) h1f[s] = g_h1[n * 12 + s] + g_acc1[n * 12 + s] * inv;
    float* o = out + (size_t)n * 128;
    #pragma unroll 4
    for (int c = 0; c < 32; c++) {
        float f0 = 0.f;
        #pragma unroll
        for (int s = 0; s < 16; s++) f0 = fmaf(h0f[s], lin0[s * 32 + c], f0);
        o[4 * c] = 0.25f * f0;                 // 1/sqrt(16)
        #pragma unroll
        for (int m = 0; m < 3; m++) {
            float f1 = 0.f;
            #pragma unroll
            for (int v = 0; v < 4; v++) f1 = fmaf(h1f[v * 3 + m], lin1[v * 32 + c], f1);
            o[4 * c + 1 + m] = 0.5f * f1;      // 1/sqrt(4)
        }
    }
}

// ---------------- launch ----------------
extern "C" void kernel_launch(void* const* d_in, const int* in_sizes, int n_in,
                              void* d_out, int out_size) {
    const float* pos          = (const float*)d_in[0];
    const float* node_feats   = (const float*)d_in[1];
    const float* edge_attr_in = (const float*)d_in[2];
    const int*   edge_index   = (const int*)d_in[3];
    const float* enc_W  = (const float*)d_in[4];
    const float* enc_b  = (const float*)d_in[5];
    const float* ne_W1  = (const float*)d_in[6];
    const float* ne_b1  = (const float*)d_in[7];
    const float* ne_W2  = (const float*)d_in[8];
    const float* ne_b2  = (const float*)d_in[9];
    const float* ee_W1  = (const float*)d_in[10];
    const float* ee_b1  = (const float*)d_in[11];
    const float* ee_W2  = (const float*)d_in[12];
    const float* ee_b2  = (const float*)d_in[13];
    const float* re_W1  = (const float*)d_in[14];
    const float* re_b1  = (const float*)d_in[15];
    const float* re_W2  = (const float*)d_in[16];
    const float* re_b2  = (const float*)d_in[17];
    const float* fc1_W  = (const float*)d_in[18];   // [2,48,64]
    const float* fc1_b  = (const float*)d_in[19];   // [2,64]
    const float* fc2_W  = (const float*)d_in[20];   // [2,64,416]
    const float* fc2_b  = (const float*)d_in[21];   // [2,416]
    const float* lin0_W = (const float*)d_in[22];
    const float* lin1_W = (const float*)d_in[23];
    float* out = (float*)d_out;

    int dev = 0;
    cudaGetDevice(&dev);
    int nsm = 148;
    cudaDeviceGetAttribute(&nsm, cudaDevAttrMultiProcessorCount, dev);
    cudaFuncSetAttribute(conv_kernel, cudaFuncAttributeMaxDynamicSharedMemorySize, cfg::SMEM_BYTES);

    zero_kernel<<<256, 256>>>();
    node_init_kernel<<<(cfg::NN + 127) / 128, 128>>>(node_feats, enc_W, enc_b,
                                                     ne_W1, ne_b1, ne_W2, ne_b2);
    edge_init_kernel<<<(cfg::NE + 127) / 128, 128>>>(pos, edge_attr_in, edge_index,
                                                     ee_W1, ee_b1, ee_W2, ee_b2,
                                                     re_W1, re_b1, re_W2, re_b2);
    // layer 0
    conv_kernel<<<nsm, cfg::CONV_THREADS, cfg::SMEM_BYTES>>>(edge_index,
        fc1_W, fc1_b, fc2_W, fc2_b);
    update_kernel<<<(cfg::NN * 16 + 255) / 256, 256>>>();
    // layer 1
    conv_kernel<<<nsm, cfg::CONV_THREADS, cfg::SMEM_BYTES>>>(edge_index,
        fc1_W + 48 * 64, fc1_b + 64, fc2_W + 64 * 416, fc2_b + 416);
    // final update + output projection
    final_kernel<<<(cfg::NN + 127) / 128, 128>>>(out, lin0_W, lin1_W);
}